// round 10
// baseline (speedup 1.0000x reference)
#include <cuda_runtime.h>
#include <cuda_bf16.h>
#include <stdint.h>

#define NUM_ROWS 16384
#define HDIM     2048
#define KSEL     4
#define NEXP     64
#define NTOT     (NUM_ROWS * KSEL)   /* 65536 expanded slots */
#define NSETUP   128                 /* setup blocks               */
#define CHK      512                 /* items per setup chunk      */

/* output layout (floats) */
#define X_OFF   0
#define RI_OFF  ((size_t)NTOT * HDIM)                 /* 134217728 */
#define CNT_OFF (RI_OFF + NTOT)                        /* +65536 */
#define SC_OFF  (CNT_OFF + NEXP)                       /* +64 */

/* scratch (no cudaMalloc allowed) */
__device__ int g_counts[NSETUP * NEXP];   /* counts -> stable bases */
__device__ int g_rank[NTOT];              /* intra-chunk stable rank */
__device__ unsigned g_sticket = 0;        /* setup arrival ticket (monotonic) */
__device__ unsigned g_cticket = 0;        /* all-block ticket -> epoch        */
__device__ unsigned g_release = 0;        /* bumped once per launch           */

__global__ void __launch_bounds__(128) k_fused(const float* __restrict__ x,
                                               const int* __restrict__ eidx,
                                               const float* __restrict__ scale,
                                               float* __restrict__ out) {
    __shared__ int whist[4][NEXP];
    __shared__ int offs[NEXP];
    __shared__ unsigned s_epoch;
    __shared__ int s_last;
    __shared__ int s_ready;

    int t = threadIdx.x;
    int b = blockIdx.x;
    int w = t >> 5, lane = t & 31;

    /* epoch: one atomic per block; counter advances by NTOT per launch */
    if (t == 0) s_epoch = atomicAdd(&g_cticket, 1u) / (unsigned)NTOT;
    __syncthreads();
    unsigned epoch = s_epoch;

    /* ================= setup (blocks 0..NSETUP-1) ================= */
    if (b < NSETUP) {
        ((int*)whist)[t] = 0;
        ((int*)whist)[t + 128] = 0;
        __syncthreads();

        int I0 = b * CHK;
        int myrank[4], e_arr[4];
        /* position-major: item index = I0 + w*128 + p*32 + lane */
#pragma unroll
        for (int p = 0; p < 4; ++p) {
            int e = eidx[I0 + w * 128 + p * 32 + lane];
            e_arr[p] = e;
            unsigned m = __match_any_sync(0xffffffffu, e);
            int r = __popc(m & ((1u << lane) - 1));
            myrank[p] = whist[w][e] + r;
            __syncwarp();
            if (r == 0) whist[w][e] += __popc(m);
            __syncwarp();
        }
        __syncthreads();
#pragma unroll
        for (int p = 0; p < 4; ++p) {
            int e = e_arr[p];
            int off = 0;
#pragma unroll
            for (int w2 = 0; w2 < 4; ++w2)
                if (w2 < w) off += whist[w2][e];
            g_rank[I0 + w * 128 + p * 32 + lane] = off + myrank[p];
        }
        if (t < NEXP)
            g_counts[b * NEXP + t] =
                whist[0][t] + whist[1][t] + whist[2][t] + whist[3][t];
        __threadfence();
        __syncthreads();

        if (t == 0) {
            unsigned st = atomicAdd(&g_sticket, 1u);
            s_last = ((st % NSETUP) == NSETUP - 1);
        }
        __syncthreads();

        if (s_last) {
            __threadfence();   /* acquire all counts */
            /* scan: e2 = t>>1 (expert), g2 = t&1 owns 64 chunks; two-pass
             * (no register array -> keeps whole-kernel reg count low) */
            int e2 = t >> 1, g2 = t & 1;
            int partial = 0;
#pragma unroll 8
            for (int j = 0; j < 64; ++j)
                partial += g_counts[(g2 * 64 + j) * NEXP + e2];
            int inc = partial;
            {
                int y = __shfl_up_sync(0xffffffffu, inc, 1, 2);
                if (g2 >= 1) inc += y;
            }
            if (g2 == 1) whist[0][e2] = inc;   /* totals */
            __syncthreads();
            if (t == 0) {
                int run = 0;
                for (int j = 0; j < NEXP; ++j) { offs[j] = run; run += whist[0][j]; }
            }
            __syncthreads();
            if (t < NEXP) out[CNT_OFF + t] = (float)whist[0][t];

            int run = offs[e2] + (inc - partial);
#pragma unroll 8
            for (int j = 0; j < 64; ++j) {
                int idx2 = (g2 * 64 + j) * NEXP + e2;
                int v = g_counts[idx2];
                g_counts[idx2] = run;
                run += v;
            }
            __threadfence();
            __syncthreads();
            if (t == 0) atomicAdd(&g_release, 1u);
        }
    }

    /* ================= copy (every block: slot i = b) ================= */
    int i = b;
    int src = i >> 2;
    const float4* __restrict__ s4 = (const float4*)(x + (size_t)src * HDIM);

    if (t == 0)
        s_ready = (*(volatile unsigned*)&g_release > epoch) ? 1 : 0;
    __syncthreads();

    if (s_ready) {
        /* fast path: proven interleaved pattern */
        __threadfence();
        int e = __ldg(eidx + i);
        int d = g_counts[(i >> 9) * NEXP + e] + g_rank[i];
        float4* __restrict__ o = (float4*)(out + X_OFF + (size_t)d * HDIM);
#pragma unroll
        for (int j = 0; j < 4; ++j) {
            int idx = t + j * 128;
            o[idx] = s4[idx];
        }
        if (t == 0) {
            out[RI_OFF + i] = (float)d;
            out[SC_OFF + d] = scale[src];
        }
    } else {
        /* slow path (wave-1 only): pre-load x while setup finishes */
        float4 v0 = s4[t];
        float4 v1 = s4[t + 128];
        float4 v2 = s4[t + 256];
        float4 v3 = s4[t + 384];
        int e = __ldg(eidx + i);
        if (t == 0) {
            while (*(volatile unsigned*)&g_release <= epoch) { }
        }
        __syncthreads();
        __threadfence();
        int d = g_counts[(i >> 9) * NEXP + e] + g_rank[i];
        float4* __restrict__ o = (float4*)(out + X_OFF + (size_t)d * HDIM);
        o[t]       = v0;
        o[t + 128] = v1;
        o[t + 256] = v2;
        o[t + 384] = v3;
        if (t == 0) {
            out[RI_OFF + i] = (float)d;
            out[SC_OFF + d] = scale[src];
        }
    }
}

extern "C" void kernel_launch(void* const* d_in, const int* in_sizes, int n_in,
                              void* d_out, int out_size) {
    const float* x     = (const float*)d_in[0];
    const int*   eidx  = (const int*)d_in[1];
    const float* scale = (const float*)d_in[2];
    float* out = (float*)d_out;

    k_fused<<<NTOT, 128>>>(x, eidx, scale, out);
}

// round 11
// speedup vs baseline: 1.1355x; 1.1355x over previous
#include <cuda_runtime.h>
#include <cuda_bf16.h>
#include <stdint.h>

#define NUM_ROWS 16384
#define HDIM     2048
#define KSEL     4
#define NEXP     64
#define NTOT     (NUM_ROWS * KSEL)   /* 65536 expanded slots */
#define NCHUNK   512
#define CHUNK    (NTOT / NCHUNK)     /* 128 items per chunk */
#define NWARP    (CHUNK / 32)        /* 4 warps per chunk */

/* output layout (floats) */
#define X_OFF   0
#define RI_OFF  ((size_t)NTOT * HDIM)                 /* 134217728 */
#define CNT_OFF (RI_OFF + NTOT)                        /* +65536 */
#define SC_OFF  (CNT_OFF + NEXP)                       /* +64 */

/* scratch (no cudaMalloc allowed) */
__device__ int g_chunkCounts[NCHUNK * NEXP];  /* counts -> stable bases */
__device__ int g_rank[NTOT];                  /* intra-chunk stable rank */
__device__ unsigned g_ticket = 0;             /* monotonic across replays */

/* ---- K1: histogram + stable rank; LAST-arriving block also scans ---- */
__global__ void __launch_bounds__(CHUNK) k_setup(const int* __restrict__ eidx,
                                                 float* __restrict__ out) {
    __shared__ int shcnt[NWARP][NEXP];
    __shared__ int offs[NEXP];
    __shared__ int s_last;

    int t = threadIdx.x;
    int c = blockIdx.x;
    int w = t >> 5, lane = t & 31;

    for (int j = t; j < NWARP * NEXP; j += CHUNK)
        ((int*)shcnt)[j] = 0;
    __syncthreads();

    int i = c * CHUNK + t;
    int e = eidx[i];
    unsigned m = __match_any_sync(0xffffffffu, e);
    int rank = __popc(m & ((1u << lane) - 1));
    if (rank == 0) shcnt[w][e] = __popc(m);
    __syncthreads();

    int off = 0;
#pragma unroll
    for (int w2 = 0; w2 < NWARP; ++w2)
        if (w2 < w) off += shcnt[w2][e];
    g_rank[i] = off + rank;

    if (t < NEXP) {
        int s = 0;
#pragma unroll
        for (int w2 = 0; w2 < NWARP; ++w2) s += shcnt[w2][t];
        g_chunkCounts[c * NEXP + t] = s;
    }
    __threadfence();
    __syncthreads();

    if (t == 0) {
        unsigned ticket = atomicAdd(&g_ticket, 1u);
        s_last = ((ticket % NCHUNK) == NCHUNK - 1);
    }
    __syncthreads();
    if (!s_last) return;

    /* ---- last block (128 threads): scan over 512 chunks ---- */
    __threadfence();
    int e2 = t >> 1;          /* expert 0..63 */
    int g2 = t & 1;           /* half 0..1, each owns 256 chunks */
    int partial = 0;
#pragma unroll 8
    for (int j = 0; j < 256; ++j)
        partial += g_chunkCounts[(g2 * 256 + j) * NEXP + e2];

    int inc = partial;
    {
        int y = __shfl_up_sync(0xffffffffu, inc, 1, 2);
        if (g2 >= 1) inc += y;
    }
    if (g2 == 1) shcnt[0][e2] = inc;   /* totals */
    __syncthreads();
    if (t == 0) {
        int run = 0;
        for (int j = 0; j < NEXP; ++j) { offs[j] = run; run += shcnt[0][j]; }
    }
    __syncthreads();
    if (t < NEXP) out[CNT_OFF + t] = (float)shcnt[0][t];

    int run = offs[e2] + (inc - partial);
#pragma unroll 8
    for (int j = 0; j < 256; ++j) {
        int idx = (g2 * 256 + j) * NEXP + e2;
        int v = g_chunkCounts[idx];
        g_chunkCounts[idx] = run;
        run += v;
    }
}

/* ---- K2: gather copy; 2 rows per block, two independent 128-thr halves,
 * each half = the PROVEN interleaved load->store per-row pattern. ---- */
__global__ void __launch_bounds__(256) k_copy(const float* __restrict__ x,
                                              const int* __restrict__ eidx,
                                              const float* __restrict__ scale,
                                              float* __restrict__ out) {
#if __CUDA_ARCH__ >= 900
    cudaGridDependencySynchronize();
#endif
    int half = threadIdx.x >> 7;            /* 0 or 1 */
    int t    = threadIdx.x & 127;
    int i = blockIdx.x * 2 + half;          /* expanded slot */
    int e = __ldg(eidx + i);
    int d = g_chunkCounts[(i >> 7) * NEXP + e] + g_rank[i];
    int src = i >> 2;

    const float4* __restrict__ s = (const float4*)(x + (size_t)src * HDIM);
    float4* __restrict__ o = (float4*)(out + X_OFF + (size_t)d * HDIM);
#pragma unroll
    for (int j = 0; j < 4; ++j) {
        int idx = t + j * 128;   /* 512 float4 per row */
        o[idx] = s[idx];
    }
    if (t == 0) {
        out[RI_OFF + i] = (float)d;
        out[SC_OFF + d] = scale[src];
    }
}

extern "C" void kernel_launch(void* const* d_in, const int* in_sizes, int n_in,
                              void* d_out, int out_size) {
    const float* x     = (const float*)d_in[0];
    const int*   eidx  = (const int*)d_in[1];
    const float* scale = (const float*)d_in[2];
    float* out = (float*)d_out;

    k_setup<<<NCHUNK, CHUNK>>>(eidx, out);

    cudaLaunchAttribute attr[1];
    attr[0].id = cudaLaunchAttributeProgrammaticStreamSerialization;
    attr[0].val.programmaticStreamSerializationAllowed = 1;

    cudaLaunchConfig_t cfg = {};
    cfg.gridDim  = dim3(NTOT / 2, 1, 1);
    cfg.blockDim = dim3(256, 1, 1);
    cfg.dynamicSmemBytes = 0;
    cfg.stream = 0;
    cfg.attrs = attr;
    cfg.numAttrs = 1;
    cudaLaunchKernelEx(&cfg, k_copy, x, eidx, scale, out);
}